// round 11
// baseline (speedup 1.0000x reference)
#include <cuda_runtime.h>
#include <math.h>

#define B_  2
#define L_  512
#define H_  128
#define NH_ 2
#define DH_ 64
#define RV_ 257   // REL_VOCAB
#define SP  512   // score row pitch
#define RVP 320   // rel-vocab row pitch (5*64)
#define BH_ (B_ * NH_)

// Scratch (allocation-free rule: __device__ globals)
__device__ float g_Q[B_ * L_ * H_];   // pre-scaled by 0.125
__device__ float g_K[B_ * L_ * H_];
__device__ float g_V[B_ * L_ * H_];
__device__ float g_O[B_ * L_ * H_];
__device__ float g_S[BH_ * L_ * SP];    // scores, then softmax weights (in place)
__device__ float g_RS[BH_ * L_ * RVP];  // q . E_RK[r]
__device__ float g_WS[BH_ * L_ * RVP];  // weight histogram over rel vocab

// ---------------------------------------------------------------------------
// Kernel 1: QKV projections as 64x64 register-tiled GEMM.
// grid = (16 row-tiles, 2 col-tiles, 3 matrices), 256 threads.
//   Y[r][o] = sum_k X[r][k] * W[o][k]  (+ bias[o] + E[poss[r]][o]; Q scaled)
// Both operands k-major -> score_gemm-style inner loop (8 LDS.128 / 64 FMA).
// ---------------------------------------------------------------------------
__global__ __launch_bounds__(256) void qkv_gemm(
    const float* __restrict__ query, const float* __restrict__ key,
    const float* __restrict__ value,
    const float* __restrict__ Wq, const float* __restrict__ bq,
    const float* __restrict__ Wk, const float* __restrict__ bk,
    const float* __restrict__ Wv, const float* __restrict__ bv,
    const float* __restrict__ E_PK, const float* __restrict__ E_PV,
    const int* __restrict__ poss)
{
    const int m = blockIdx.z;
    const float *X, *W, *bias, *E;
    float* Y;
    if (m == 0)      { X = query; W = Wq; bias = bq; E = nullptr; Y = g_Q; }
    else if (m == 1) { X = key;   W = Wk; bias = bk; E = E_PK;    Y = g_K; }
    else             { X = value; W = Wv; bias = bv; E = E_PV;    Y = g_V; }

    const int r0 = blockIdx.x * 64;
    const int o0 = blockIdx.y * 64;
    const int tid = threadIdx.x;
    const int tx = tid & 15, ty = tid >> 4;

    __shared__ float As[64 * 68];
    __shared__ float Bs[64 * 68];

    float acc[4][4];
    #pragma unroll
    for (int ii = 0; ii < 4; ii++)
        #pragma unroll
        for (int jj = 0; jj < 4; jj++) acc[ii][jj] = 0.f;

    #pragma unroll
    for (int kc0 = 0; kc0 < H_; kc0 += 64) {
        // stage 64x64 chunks of X and W (coalesced float4)
        #pragma unroll
        for (int p = 0; p < 4; p++) {
            int f = tid + 256 * p;
            int row = f >> 4, c4 = f & 15;
            *(float4*)(As + row * 68 + 4 * c4) =
                ((const float4*)(X + (size_t)(r0 + row) * H_ + kc0))[c4];
            *(float4*)(Bs + row * 68 + 4 * c4) =
                ((const float4*)(W + (size_t)(o0 + row) * H_ + kc0))[c4];
        }
        __syncthreads();

        #pragma unroll 4
        for (int kc = 0; kc < 16; kc++) {
            float4 a[4], bb[4];
            #pragma unroll
            for (int u = 0; u < 4; u++) {
                a[u]  = *(const float4*)(As + (4 * ty + u) * 68 + 4 * kc);
                bb[u] = *(const float4*)(Bs + (4 * tx + u) * 68 + 4 * kc);
            }
            #pragma unroll
            for (int ii = 0; ii < 4; ii++)
                #pragma unroll
                for (int jj = 0; jj < 4; jj++) {
                    acc[ii][jj] = fmaf(a[ii].x, bb[jj].x, acc[ii][jj]);
                    acc[ii][jj] = fmaf(a[ii].y, bb[jj].y, acc[ii][jj]);
                    acc[ii][jj] = fmaf(a[ii].z, bb[jj].z, acc[ii][jj]);
                    acc[ii][jj] = fmaf(a[ii].w, bb[jj].w, acc[ii][jj]);
                }
        }
        __syncthreads();
    }

    // epilogue: bias, positional embedding gather, Q scale
    const float scale = (m == 0) ? 0.125f : 1.0f;
    float4 b4 = *(const float4*)(bias + o0 + 4 * tx);
    #pragma unroll
    for (int ii = 0; ii < 4; ii++) {
        int gi = r0 + 4 * ty + ii;
        float4 v = make_float4(acc[ii][0] + b4.x, acc[ii][1] + b4.y,
                               acc[ii][2] + b4.z, acc[ii][3] + b4.w);
        if (E) {
            float4 e = *(const float4*)(E + (size_t)poss[gi] * H_ + o0 + 4 * tx);
            v.x += e.x; v.y += e.y; v.z += e.z; v.w += e.w;
        }
        v.x *= scale; v.y *= scale; v.z *= scale; v.w *= scale;
        *(float4*)(Y + (size_t)gi * H_ + o0 + 4 * tx) = v;
    }
}

// ---------------------------------------------------------------------------
// Kernel A: score GEMMs. grid = (8, 13, 4). (unchanged from R10)
// ---------------------------------------------------------------------------
__global__ __launch_bounds__(256) void score_gemm(const float* __restrict__ E_RK)
{
    const int it = blockIdx.x;
    const int yy = blockIdx.y;
    const int bh = blockIdx.z;
    const bool smode = (yy < 8);
    const int jt = smode ? yy : (yy - 8);
    if (smode && jt > it) return;

    const int b = bh >> 1, h = bh & 1, hd = h * DH_;
    const int i0 = it * 64;
    const int j0 = jt * 64;

    __shared__ float As[64 * 68];
    __shared__ float Bs[64 * 68];

    const int tid = threadIdx.x;

    const float* Asrc = g_Q + ((size_t)(b * L_ + i0)) * H_ + hd;
    #pragma unroll
    for (int p = 0; p < 4; p++) {
        int f = tid + 256 * p;
        int row = f >> 4, c4 = f & 15;
        float4 va = ((const float4*)(Asrc + (size_t)row * H_))[c4];
        *(float4*)(As + row * 68 + 4 * c4) = va;
        float4 vb;
        if (smode) {
            vb = ((const float4*)(g_K + ((size_t)(b * L_ + j0 + row)) * H_ + hd))[c4];
        } else {
            int r = j0 + row;
            vb = (r < RV_)
               ? ((const float4*)(E_RK + (size_t)r * H_ + hd))[c4]
               : make_float4(0.f, 0.f, 0.f, 0.f);
        }
        *(float4*)(Bs + row * 68 + 4 * c4) = vb;
    }
    __syncthreads();

    const int tx = tid & 15, ty = tid >> 4;
    float acc[4][4];
    #pragma unroll
    for (int ii = 0; ii < 4; ii++)
        #pragma unroll
        for (int jj = 0; jj < 4; jj++) acc[ii][jj] = 0.f;

    #pragma unroll 4
    for (int kc = 0; kc < 16; kc++) {
        float4 a[4], bb[4];
        #pragma unroll
        for (int u = 0; u < 4; u++) {
            a[u]  = *(const float4*)(As + (4 * ty + u) * 68 + 4 * kc);
            bb[u] = *(const float4*)(Bs + (4 * tx + u) * 68 + 4 * kc);
        }
        #pragma unroll
        for (int ii = 0; ii < 4; ii++)
            #pragma unroll
            for (int jj = 0; jj < 4; jj++) {
                acc[ii][jj] = fmaf(a[ii].x, bb[jj].x, acc[ii][jj]);
                acc[ii][jj] = fmaf(a[ii].y, bb[jj].y, acc[ii][jj]);
                acc[ii][jj] = fmaf(a[ii].z, bb[jj].z, acc[ii][jj]);
                acc[ii][jj] = fmaf(a[ii].w, bb[jj].w, acc[ii][jj]);
            }
    }

    #pragma unroll
    for (int ii = 0; ii < 4; ii++) {
        int gi = i0 + 4 * ty + ii;
        float4 v = make_float4(acc[ii][0], acc[ii][1], acc[ii][2], acc[ii][3]);
        if (smode)
            *(float4*)(g_S + ((size_t)bh * L_ + gi) * SP + j0 + 4 * tx) = v;
        else
            *(float4*)(g_RS + ((size_t)bh * L_ + gi) * RVP + j0 + 4 * tx) = v;
    }
}

// ---------------------------------------------------------------------------
// Kernel B: softmax + rel lookup + histogram. (unchanged from R10)
// ---------------------------------------------------------------------------
__global__ __launch_bounds__(256) void softmax_kernel(const int* __restrict__ interval)
{
    const int i = blockIdx.x;
    const int h = blockIdx.y;
    const int b = blockIdx.z;
    const int bh = b * NH_ + h;
    const int tid = threadIdx.x;
    const int warp = tid >> 5, lane = tid & 31;
    const int n = i + 1;
    const int jpad = ((i >> 6) + 1) * 64;

    __shared__ float rsr[RV_];
    __shared__ float ws[RVP];
    __shared__ float sc[L_];
    __shared__ int   idxs[L_];
    __shared__ float red[8];

    const float* RSrow = g_RS + ((size_t)bh * L_ + i) * RVP;
    for (int r = tid; r < RV_; r += 256) rsr[r] = RSrow[r];
    for (int r = tid; r < RVP; r += 256) ws[r] = 0.f;
    {
        const int* iv = interval + ((size_t)(b * L_ + i)) * L_;
        for (int j = tid; j < n; j += 256) idxs[j] = iv[j];
    }
    if (tid < DH_)
        g_O[((size_t)(b * L_ + i)) * H_ + h * DH_ + tid] = 0.f;
    __syncthreads();

    float* Srow = g_S + ((size_t)bh * L_ + i) * SP;

    float m = -INFINITY;
    for (int j = tid; j < n; j += 256) {
        float s = Srow[j] + rsr[idxs[j]];
        sc[j] = s;
        m = fmaxf(m, s);
    }
    #pragma unroll
    for (int off = 16; off > 0; off >>= 1)
        m = fmaxf(m, __shfl_xor_sync(0xffffffffu, m, off));
    if (lane == 0) red[warp] = m;
    __syncthreads();
    m = fmaxf(fmaxf(fmaxf(red[0], red[1]), fmaxf(red[2], red[3])),
              fmaxf(fmaxf(red[4], red[5]), fmaxf(red[6], red[7])));

    float s = 0.f;
    for (int j = tid; j < n; j += 256) {
        float e = __expf(sc[j] - m);
        sc[j] = e;
        s += e;
    }
    #pragma unroll
    for (int off = 16; off > 0; off >>= 1)
        s += __shfl_xor_sync(0xffffffffu, s, off);
    __syncthreads();
    if (lane == 0) red[warp] = s;
    __syncthreads();
    float inv = 1.f / ((red[0] + red[1]) + (red[2] + red[3]) +
                       (red[4] + red[5]) + (red[6] + red[7]));

    for (int j = tid; j < n; j += 256) {
        float w = sc[j] * inv;
        Srow[j] = w;
        atomicAdd(&ws[idxs[j]], w);
    }
    for (int j = n + tid; j < jpad; j += 256) Srow[j] = 0.f;
    __syncthreads();

    float* WSrow = g_WS + ((size_t)bh * L_ + i) * RVP;
    for (int r = tid; r < RVP; r += 256) WSrow[r] = ws[r];
}

// ---------------------------------------------------------------------------
// Kernel C: output GEMMs, atomic split-k. grid = (8, 13, 4).
// Inner loop rewritten: 4-k batched, 8 LDS.128 per 64 FMA.
// ---------------------------------------------------------------------------
__global__ __launch_bounds__(256) void out_gemm(const float* __restrict__ E_RV)
{
    const int it = blockIdx.x;
    const int yy = blockIdx.y;
    const int bh = blockIdx.z;
    const bool smode = (yy < 8);
    const int jt = smode ? yy : (yy - 8);
    if (smode && jt > it) return;

    const int b = bh >> 1, h = bh & 1, hd = h * DH_;
    const int i0 = it * 64;
    const int k0 = jt * 64;

    __shared__ float Ws[64 * 68];   // W tile: [i][k], k-contiguous
    __shared__ float Vs[64 * 68];   // V tile: [k][d]

    const int tid = threadIdx.x;

    #pragma unroll
    for (int p = 0; p < 4; p++) {
        int f = tid + 256 * p;
        int row = f >> 4, c4 = f & 15;
        float4 vw, vv;
        if (smode) {
            vw = *(const float4*)(g_S + ((size_t)bh * L_ + i0 + row) * SP + k0 + 4 * c4);
            vv = ((const float4*)(g_V + ((size_t)(b * L_ + k0 + row)) * H_ + hd))[c4];
        } else {
            vw = *(const float4*)(g_WS + ((size_t)bh * L_ + i0 + row) * RVP + k0 + 4 * c4);
            int r = k0 + row;
            vv = (r < RV_)
               ? ((const float4*)(E_RV + (size_t)r * H_ + hd))[c4]
               : make_float4(0.f, 0.f, 0.f, 0.f);
        }
        *(float4*)(Ws + row * 68 + 4 * c4) = vw;
        *(float4*)(Vs + row * 68 + 4 * c4) = vv;
    }
    __syncthreads();

    const int tx = tid & 15, ty = tid >> 4;
    float acc[4][4];
    #pragma unroll
    for (int ii = 0; ii < 4; ii++)
        #pragma unroll
        for (int jj = 0; jj < 4; jj++) acc[ii][jj] = 0.f;

    #pragma unroll 4
    for (int kc = 0; kc < 16; kc++) {
        float4 a[4];    // a[ii] = W[i=4ty+ii][k=4kc..4kc+3]
        float4 bv[4];   // bv[kk] = V[k=4kc+kk][d=4tx..4tx+3]
        #pragma unroll
        for (int u = 0; u < 4; u++) {
            a[u]  = *(const float4*)(Ws + (4 * ty + u) * 68 + 4 * kc);
            bv[u] = *(const float4*)(Vs + (4 * kc + u) * 68 + 4 * tx);
        }
        #pragma unroll
        for (int ii = 0; ii < 4; ii++) {
            acc[ii][0] = fmaf(a[ii].x, bv[0].x, acc[ii][0]);
            acc[ii][1] = fmaf(a[ii].x, bv[0].y, acc[ii][1]);
            acc[ii][2] = fmaf(a[ii].x, bv[0].z, acc[ii][2]);
            acc[ii][3] = fmaf(a[ii].x, bv[0].w, acc[ii][3]);
            acc[ii][0] = fmaf(a[ii].y, bv[1].x, acc[ii][0]);
            acc[ii][1] = fmaf(a[ii].y, bv[1].y, acc[ii][1]);
            acc[ii][2] = fmaf(a[ii].y, bv[1].z, acc[ii][2]);
            acc[ii][3] = fmaf(a[ii].y, bv[1].w, acc[ii][3]);
            acc[ii][0] = fmaf(a[ii].z, bv[2].x, acc[ii][0]);
            acc[ii][1] = fmaf(a[ii].z, bv[2].y, acc[ii][1]);
            acc[ii][2] = fmaf(a[ii].z, bv[2].z, acc[ii][2]);
            acc[ii][3] = fmaf(a[ii].z, bv[2].w, acc[ii][3]);
            acc[ii][0] = fmaf(a[ii].w, bv[3].x, acc[ii][0]);
            acc[ii][1] = fmaf(a[ii].w, bv[3].y, acc[ii][1]);
            acc[ii][2] = fmaf(a[ii].w, bv[3].z, acc[ii][2]);
            acc[ii][3] = fmaf(a[ii].w, bv[3].w, acc[ii][3]);
        }
    }

    #pragma unroll
    for (int ii = 0; ii < 4; ii++) {
        float* orow = g_O + ((size_t)(b * L_ + i0 + 4 * ty + ii)) * H_ + hd + 4 * tx;
        #pragma unroll
        for (int jj = 0; jj < 4; jj++)
            atomicAdd(orow + jj, acc[ii][jj]);
    }
}

// ---------------------------------------------------------------------------
// Kernel 3: output projection as 64x64 tiled GEMM + NaN guard.
// grid = (16, 2), 256 threads.
// ---------------------------------------------------------------------------
__global__ __launch_bounds__(256) void proj_gemm(
    const float* __restrict__ Wo, const float* __restrict__ bo,
    float* __restrict__ out)
{
    const int r0 = blockIdx.x * 64;
    const int o0 = blockIdx.y * 64;
    const int tid = threadIdx.x;
    const int tx = tid & 15, ty = tid >> 4;

    __shared__ float As[64 * 68];
    __shared__ float Bs[64 * 68];

    float acc[4][4];
    #pragma unroll
    for (int ii = 0; ii < 4; ii++)
        #pragma unroll
        for (int jj = 0; jj < 4; jj++) acc[ii][jj] = 0.f;

    #pragma unroll
    for (int kc0 = 0; kc0 < H_; kc0 += 64) {
        #pragma unroll
        for (int p = 0; p < 4; p++) {
            int f = tid + 256 * p;
            int row = f >> 4, c4 = f & 15;
            *(float4*)(As + row * 68 + 4 * c4) =
                ((const float4*)(g_O + (size_t)(r0 + row) * H_ + kc0))[c4];
            *(float4*)(Bs + row * 68 + 4 * c4) =
                ((const float4*)(Wo + (size_t)(o0 + row) * H_ + kc0))[c4];
        }
        __syncthreads();

        #pragma unroll 4
        for (int kc = 0; kc < 16; kc++) {
            float4 a[4], bb[4];
            #pragma unroll
            for (int u = 0; u < 4; u++) {
                a[u]  = *(const float4*)(As + (4 * ty + u) * 68 + 4 * kc);
                bb[u] = *(const float4*)(Bs + (4 * tx + u) * 68 + 4 * kc);
            }
            #pragma unroll
            for (int ii = 0; ii < 4; ii++)
                #pragma unroll
                for (int jj = 0; jj < 4; jj++) {
                    acc[ii][jj] = fmaf(a[ii].x, bb[jj].x, acc[ii][jj]);
                    acc[ii][jj] = fmaf(a[ii].y, bb[jj].y, acc[ii][jj]);
                    acc[ii][jj] = fmaf(a[ii].z, bb[jj].z, acc[ii][jj]);
                    acc[ii][jj] = fmaf(a[ii].w, bb[jj].w, acc[ii][jj]);
                }
        }
        __syncthreads();
    }

    float4 b4 = *(const float4*)(bo + o0 + 4 * tx);
    #pragma unroll
    for (int ii = 0; ii < 4; ii++) {
        int gi = r0 + 4 * ty + ii;
        float v0 = acc[ii][0] + b4.x;
        float v1 = acc[ii][1] + b4.y;
        float v2 = acc[ii][2] + b4.z;
        float v3 = acc[ii][3] + b4.w;
        if (isnan(v0)) v0 = 0.f;
        if (isnan(v1)) v1 = 0.f;
        if (isnan(v2)) v2 = 0.f;
        if (isnan(v3)) v3 = 0.f;
        *(float4*)(out + (size_t)gi * H_ + o0 + 4 * tx) =
            make_float4(v0, v1, v2, v3);
    }
}

// ---------------------------------------------------------------------------
extern "C" void kernel_launch(void* const* d_in, const int* in_sizes, int n_in,
                              void* d_out, int out_size)
{
    const float* query    = (const float*)d_in[0];
    const float* key      = (const float*)d_in[1];
    const float* value    = (const float*)d_in[2];
    const float* Wq       = (const float*)d_in[3];
    const float* bq       = (const float*)d_in[4];
    const float* Wk       = (const float*)d_in[5];
    const float* bk       = (const float*)d_in[6];
    const float* Wv       = (const float*)d_in[7];
    const float* bv       = (const float*)d_in[8];
    const float* Wo       = (const float*)d_in[9];
    const float* bo       = (const float*)d_in[10];
    const float* E_PK     = (const float*)d_in[11];
    const float* E_PV     = (const float*)d_in[12];
    const float* E_RK     = (const float*)d_in[13];
    const float* E_RV     = (const float*)d_in[14];
    const int*   poss     = (const int*)d_in[15];
    const int*   interval = (const int*)d_in[16];
    // d_in[17] = attn_mask (exactly tril; causal is hardcoded)

    float* out = (float*)d_out;

    dim3 qgrid(16, 2, 3);
    qkv_gemm<<<qgrid, 256>>>(
        query, key, value, Wq, bq, Wk, bk, Wv, bv, E_PK, E_PV, poss);

    dim3 ggrid(8, 13, BH_);
    score_gemm<<<ggrid, 256>>>(E_RK);

    dim3 sgrid(L_, NH_, B_);
    softmax_kernel<<<sgrid, 256>>>(interval);

    out_gemm<<<ggrid, 256>>>(E_RV);

    dim3 pgrid(16, 2);
    proj_gemm<<<pgrid, 256>>>(Wo, bo, out);
}

// round 12
// speedup vs baseline: 1.1515x; 1.1515x over previous
#include <cuda_runtime.h>
#include <math.h>

#define B_  2
#define L_  512
#define H_  128
#define NH_ 2
#define DH_ 64
#define RV_ 257   // REL_VOCAB
#define SP  512   // score row pitch
#define RVP 320   // rel-vocab row pitch (5*64)
#define BH_ (B_ * NH_)

// Scratch (allocation-free rule: __device__ globals)
__device__ float g_Q[B_ * L_ * H_];   // pre-scaled by 0.125
__device__ float g_K[B_ * L_ * H_];
__device__ float g_V[B_ * L_ * H_];
__device__ float g_O[B_ * L_ * H_];
__device__ float g_S[BH_ * L_ * SP];    // scores, then softmax weights (in place)
__device__ float g_RS[BH_ * L_ * RVP];  // q . E_RK[r]
__device__ float g_WS[BH_ * L_ * RVP];  // weight histogram over rel vocab

#define TM 8   // rows per GEMM block

// ---------------------------------------------------------------------------
// Kernel 1: fused QKV projections, k-split. grid = (128, 3), 256 threads.
// Thread (o, kh): half-dot over k in [kh*64, kh*64+64) for TM rows.
//   Y = X @ W^T + b  (+ E[pos] for K and V; Q scaled by 0.125)
// ---------------------------------------------------------------------------
__global__ __launch_bounds__(256) void qkv_kernel(
    const float* __restrict__ query, const float* __restrict__ key,
    const float* __restrict__ value,
    const float* __restrict__ Wq, const float* __restrict__ bq,
    const float* __restrict__ Wk, const float* __restrict__ bk,
    const float* __restrict__ Wv, const float* __restrict__ bv,
    const float* __restrict__ E_PK, const float* __restrict__ E_PV,
    const int* __restrict__ poss)
{
    const int m = blockIdx.y;
    const float *X, *W, *bias, *E;
    float* Y;
    if (m == 0)      { X = query; W = Wq; bias = bq; E = nullptr; Y = g_Q; }
    else if (m == 1) { X = key;   W = Wk; bias = bk; E = E_PK;    Y = g_K; }
    else             { X = value; W = Wv; bias = bv; E = E_PV;    Y = g_V; }

    __shared__ float4 xs[TM][32];        // TM rows x 128 floats
    __shared__ float  part[TM][H_];      // kh=1 partial sums

    const int r0 = blockIdx.x * TM;
    const int o  = threadIdx.x & 127;    // output channel
    const int kh = threadIdx.x >> 7;     // k half: 0 or 1

    // 256 float4 elements, one per thread
    ((float4*)xs)[threadIdx.x] =
        ((const float4*)(X + (size_t)r0 * H_))[threadIdx.x];
    __syncthreads();

    float acc[TM];
    #pragma unroll
    for (int rr = 0; rr < TM; rr++) acc[rr] = 0.f;

    const float4* w4p = (const float4*)(W + (size_t)o * H_) + kh * 16;
    #pragma unroll 4
    for (int c = 0; c < 16; c++) {
        float4 w = w4p[c];
        #pragma unroll
        for (int rr = 0; rr < TM; rr++) {
            float4 x = xs[rr][kh * 16 + c];
            acc[rr] = fmaf(w.x, x.x, acc[rr]);
            acc[rr] = fmaf(w.y, x.y, acc[rr]);
            acc[rr] = fmaf(w.z, x.z, acc[rr]);
            acc[rr] = fmaf(w.w, x.w, acc[rr]);
        }
    }

    if (kh == 1) {
        #pragma unroll
        for (int rr = 0; rr < TM; rr++) part[rr][o] = acc[rr];
    }
    __syncthreads();
    if (kh == 0) {
        const float scale = (m == 0) ? 0.125f : 1.0f;
        float bb = bias[o];
        #pragma unroll
        for (int rr = 0; rr < TM; rr++) {
            float v = acc[rr] + part[rr][o] + bb;
            if (E) v += E[(size_t)poss[r0 + rr] * H_ + o];
            Y[(size_t)(r0 + rr) * H_ + o] = v * scale;
        }
    }
}

// ---------------------------------------------------------------------------
// Kernel A: score GEMMs. grid = (8, 13, 4). (unchanged, R10-proven)
//   blockIdx.y < 8 : S tile  (it, jt) — causal: skip jt > it
//   blockIdx.y >= 8: RS tile (it, rt=y-8)
// ---------------------------------------------------------------------------
__global__ __launch_bounds__(256) void score_gemm(const float* __restrict__ E_RK)
{
    const int it = blockIdx.x;
    const int yy = blockIdx.y;
    const int bh = blockIdx.z;
    const bool smode = (yy < 8);
    const int jt = smode ? yy : (yy - 8);
    if (smode && jt > it) return;

    const int b = bh >> 1, h = bh & 1, hd = h * DH_;
    const int i0 = it * 64;
    const int j0 = jt * 64;

    __shared__ float As[64 * 68];
    __shared__ float Bs[64 * 68];

    const int tid = threadIdx.x;

    const float* Asrc = g_Q + ((size_t)(b * L_ + i0)) * H_ + hd;
    #pragma unroll
    for (int p = 0; p < 4; p++) {
        int f = tid + 256 * p;
        int row = f >> 4, c4 = f & 15;
        float4 va = ((const float4*)(Asrc + (size_t)row * H_))[c4];
        *(float4*)(As + row * 68 + 4 * c4) = va;
        float4 vb;
        if (smode) {
            vb = ((const float4*)(g_K + ((size_t)(b * L_ + j0 + row)) * H_ + hd))[c4];
        } else {
            int r = j0 + row;
            vb = (r < RV_)
               ? ((const float4*)(E_RK + (size_t)r * H_ + hd))[c4]
               : make_float4(0.f, 0.f, 0.f, 0.f);
        }
        *(float4*)(Bs + row * 68 + 4 * c4) = vb;
    }
    __syncthreads();

    const int tx = tid & 15, ty = tid >> 4;
    float acc[4][4];
    #pragma unroll
    for (int ii = 0; ii < 4; ii++)
        #pragma unroll
        for (int jj = 0; jj < 4; jj++) acc[ii][jj] = 0.f;

    #pragma unroll 4
    for (int kc = 0; kc < 16; kc++) {
        float4 a[4], bb[4];
        #pragma unroll
        for (int u = 0; u < 4; u++) {
            a[u]  = *(const float4*)(As + (4 * ty + u) * 68 + 4 * kc);
            bb[u] = *(const float4*)(Bs + (4 * tx + u) * 68 + 4 * kc);
        }
        #pragma unroll
        for (int ii = 0; ii < 4; ii++)
            #pragma unroll
            for (int jj = 0; jj < 4; jj++) {
                acc[ii][jj] = fmaf(a[ii].x, bb[jj].x, acc[ii][jj]);
                acc[ii][jj] = fmaf(a[ii].y, bb[jj].y, acc[ii][jj]);
                acc[ii][jj] = fmaf(a[ii].z, bb[jj].z, acc[ii][jj]);
                acc[ii][jj] = fmaf(a[ii].w, bb[jj].w, acc[ii][jj]);
            }
    }

    #pragma unroll
    for (int ii = 0; ii < 4; ii++) {
        int gi = i0 + 4 * ty + ii;
        float4 v = make_float4(acc[ii][0], acc[ii][1], acc[ii][2], acc[ii][3]);
        if (smode)
            *(float4*)(g_S + ((size_t)bh * L_ + gi) * SP + j0 + 4 * tx) = v;
        else
            *(float4*)(g_RS + ((size_t)bh * L_ + gi) * RVP + j0 + 4 * tx) = v;
    }
}

// ---------------------------------------------------------------------------
// Kernel B: softmax, warp-per-row. grid = (64, NH, B), 256 threads = 8 rows.
// Per warp (row i): s=S+RS[idx] (RS via L1 gather), softmax in registers,
// write w over S (zero-padded), warp-private smem histogram -> WS, zero O.
// No __syncthreads in the hot path.
// ---------------------------------------------------------------------------
__global__ __launch_bounds__(256) void softmax_kernel(const int* __restrict__ interval)
{
    const int tile = (L_ / 8 - 1) - (int)blockIdx.x;  // big rows first
    const int h = blockIdx.y;
    const int b = blockIdx.z;
    const int bh = b * NH_ + h;
    const int warp = threadIdx.x >> 5;
    const int lane = threadIdx.x & 31;

    const int i = tile * 8 + warp;
    const int n = i + 1;
    const int jpad = ((i >> 6) + 1) * 64;

    __shared__ float ws[8][RVP];

    // zero warp-private histogram
    for (int r = lane; r < RVP; r += 32) ws[warp][r] = 0.f;

    // zero this row's output slice for out_gemm's atomics
    {
        float* orow = g_O + ((size_t)(b * L_ + i)) * H_ + h * DH_;
        orow[lane] = 0.f;
        orow[lane + 32] = 0.f;
    }

    const int*   iv    = interval + ((size_t)(b * L_ + i)) * L_;
    const float* RSrow = g_RS + ((size_t)bh * L_ + i) * RVP;
    float*       Srow  = g_S + ((size_t)bh * L_ + i) * SP;

    float sreg[16];
    int   ireg[16];

    // pass 1: gather rel term, compute scores, running max
    float m = -INFINITY;
    #pragma unroll
    for (int t = 0; t < 16; t++) {
        int j = lane + 32 * t;
        if (j < n) {
            int idx = iv[j];
            ireg[t] = idx;
            float s = Srow[j] + RSrow[idx];
            sreg[t] = s;
            m = fmaxf(m, s);
        }
    }
    #pragma unroll
    for (int off = 16; off > 0; off >>= 1)
        m = fmaxf(m, __shfl_xor_sync(0xffffffffu, m, off));

    // pass 2: exp + sum
    float sum = 0.f;
    #pragma unroll
    for (int t = 0; t < 16; t++) {
        int j = lane + 32 * t;
        if (j < n) {
            float e = __expf(sreg[t] - m);
            sreg[t] = e;
            sum += e;
        }
    }
    #pragma unroll
    for (int off = 16; off > 0; off >>= 1)
        sum += __shfl_xor_sync(0xffffffffu, sum, off);
    float inv = 1.f / sum;

    // pass 3: normalize, write weights, histogram
    #pragma unroll
    for (int t = 0; t < 16; t++) {
        int j = lane + 32 * t;
        if (j < n) {
            float w = sreg[t] * inv;
            Srow[j] = w;
            atomicAdd(&ws[warp][ireg[t]], w);
        }
    }
    // zero-pad to tile edge
    for (int j = n + lane; j < jpad; j += 32) Srow[j] = 0.f;

    __syncwarp();

    // write histogram row
    float* WSrow = g_WS + ((size_t)bh * L_ + i) * RVP;
    for (int r = lane; r < RVP; r += 32) WSrow[r] = ws[warp][r];
}

// ---------------------------------------------------------------------------
// Kernel C: output GEMMs, atomic split-k. grid = (8, 13, 4). (R10-proven)
// ---------------------------------------------------------------------------
__global__ __launch_bounds__(256) void out_gemm(const float* __restrict__ E_RV)
{
    const int it = blockIdx.x;
    const int yy = blockIdx.y;
    const int bh = blockIdx.z;
    const bool smode = (yy < 8);
    const int jt = smode ? yy : (yy - 8);
    if (smode && jt > it) return;

    const int b = bh >> 1, h = bh & 1, hd = h * DH_;
    const int i0 = it * 64;
    const int k0 = jt * 64;

    __shared__ float Ws[64 * 68];
    __shared__ float Vs[64 * 68];

    const int tid = threadIdx.x;

    #pragma unroll
    for (int p = 0; p < 4; p++) {
        int f = tid + 256 * p;
        int row = f >> 4, c4 = f & 15;
        float4 vw, vv;
        if (smode) {
            vw = *(const float4*)(g_S + ((size_t)bh * L_ + i0 + row) * SP + k0 + 4 * c4);
            vv = ((const float4*)(g_V + ((size_t)(b * L_ + k0 + row)) * H_ + hd))[c4];
        } else {
            vw = *(const float4*)(g_WS + ((size_t)bh * L_ + i0 + row) * RVP + k0 + 4 * c4);
            int r = k0 + row;
            vv = (r < RV_)
               ? ((const float4*)(E_RV + (size_t)r * H_ + hd))[c4]
               : make_float4(0.f, 0.f, 0.f, 0.f);
        }
        *(float4*)(Ws + row * 68 + 4 * c4) = vw;
        *(float4*)(Vs + row * 68 + 4 * c4) = vv;
    }
    __syncthreads();

    const int tx = tid & 15, ty = tid >> 4;
    float acc[4][4];
    #pragma unroll
    for (int ii = 0; ii < 4; ii++)
        #pragma unroll
        for (int jj = 0; jj < 4; jj++) acc[ii][jj] = 0.f;

    #pragma unroll 8
    for (int k = 0; k < 64; k++) {
        float4 bv = *(const float4*)(Vs + k * 68 + 4 * tx);
        float a0 = Ws[(4 * ty + 0) * 68 + k];
        float a1 = Ws[(4 * ty + 1) * 68 + k];
        float a2 = Ws[(4 * ty + 2) * 68 + k];
        float a3 = Ws[(4 * ty + 3) * 68 + k];
        acc[0][0] = fmaf(a0, bv.x, acc[0][0]); acc[0][1] = fmaf(a0, bv.y, acc[0][1]);
        acc[0][2] = fmaf(a0, bv.z, acc[0][2]); acc[0][3] = fmaf(a0, bv.w, acc[0][3]);
        acc[1][0] = fmaf(a1, bv.x, acc[1][0]); acc[1][1] = fmaf(a1, bv.y, acc[1][1]);
        acc[1][2] = fmaf(a1, bv.z, acc[1][2]); acc[1][3] = fmaf(a1, bv.w, acc[1][3]);
        acc[2][0] = fmaf(a2, bv.x, acc[2][0]); acc[2][1] = fmaf(a2, bv.y, acc[2][1]);
        acc[2][2] = fmaf(a2, bv.z, acc[2][2]); acc[2][3] = fmaf(a2, bv.w, acc[2][3]);
        acc[3][0] = fmaf(a3, bv.x, acc[3][0]); acc[3][1] = fmaf(a3, bv.y, acc[3][1]);
        acc[3][2] = fmaf(a3, bv.z, acc[3][2]); acc[3][3] = fmaf(a3, bv.w, acc[3][3]);
    }

    #pragma unroll
    for (int ii = 0; ii < 4; ii++) {
        float* orow = g_O + ((size_t)(b * L_ + i0 + 4 * ty + ii)) * H_ + hd + 4 * tx;
        #pragma unroll
        for (int jj = 0; jj < 4; jj++)
            atomicAdd(orow + jj, acc[ii][jj]);
    }
}

// ---------------------------------------------------------------------------
// Kernel 3: output projection, k-split like qkv. grid = 128, 256 threads.
//   out = O @ Wo^T + bo, NaN -> 0
// ---------------------------------------------------------------------------
__global__ __launch_bounds__(256) void proj_kernel(
    const float* __restrict__ Wo, const float* __restrict__ bo,
    float* __restrict__ out)
{
    __shared__ float4 xs[TM][32];
    __shared__ float  part[TM][H_];

    const int r0 = blockIdx.x * TM;
    const int o  = threadIdx.x & 127;
    const int kh = threadIdx.x >> 7;

    ((float4*)xs)[threadIdx.x] =
        ((const float4*)(g_O + (size_t)r0 * H_))[threadIdx.x];
    __syncthreads();

    float acc[TM];
    #pragma unroll
    for (int rr = 0; rr < TM; rr++) acc[rr] = 0.f;

    const float4* w4p = (const float4*)(Wo + (size_t)o * H_) + kh * 16;
    #pragma unroll 4
    for (int c = 0; c < 16; c++) {
        float4 w = w4p[c];
        #pragma unroll
        for (int rr = 0; rr < TM; rr++) {
            float4 x = xs[rr][kh * 16 + c];
            acc[rr] = fmaf(w.x, x.x, acc[rr]);
            acc[rr] = fmaf(w.y, x.y, acc[rr]);
            acc[rr] = fmaf(w.z, x.z, acc[rr]);
            acc[rr] = fmaf(w.w, x.w, acc[rr]);
        }
    }

    if (kh == 1) {
        #pragma unroll
        for (int rr = 0; rr < TM; rr++) part[rr][o] = acc[rr];
    }
    __syncthreads();
    if (kh == 0) {
        float bb = bo[o];
        #pragma unroll
        for (int rr = 0; rr < TM; rr++) {
            float v = acc[rr] + part[rr][o] + bb;
            if (isnan(v)) v = 0.f;
            out[(size_t)(r0 + rr) * H_ + o] = v;
        }
    }
}

// ---------------------------------------------------------------------------
extern "C" void kernel_launch(void* const* d_in, const int* in_sizes, int n_in,
                              void* d_out, int out_size)
{
    const float* query    = (const float*)d_in[0];
    const float* key      = (const float*)d_in[1];
    const float* value    = (const float*)d_in[2];
    const float* Wq       = (const float*)d_in[3];
    const float* bq       = (const float*)d_in[4];
    const float* Wk       = (const float*)d_in[5];
    const float* bk       = (const float*)d_in[6];
    const float* Wv       = (const float*)d_in[7];
    const float* bv       = (const float*)d_in[8];
    const float* Wo       = (const float*)d_in[9];
    const float* bo       = (const float*)d_in[10];
    const float* E_PK     = (const float*)d_in[11];
    const float* E_PV     = (const float*)d_in[12];
    const float* E_RK     = (const float*)d_in[13];
    const float* E_RV     = (const float*)d_in[14];
    const int*   poss     = (const int*)d_in[15];
    const int*   interval = (const int*)d_in[16];
    // d_in[17] = attn_mask (exactly tril; causal is hardcoded)

    float* out = (float*)d_out;

    dim3 qgrid((B_ * L_) / TM, 3);
    qkv_kernel<<<qgrid, 256>>>(
        query, key, value, Wq, bq, Wk, bk, Wv, bv, E_PK, E_PV, poss);

    dim3 ggrid(8, 13, BH_);
    score_gemm<<<ggrid, 256>>>(E_RK);

    dim3 sgrid(L_ / 8, NH_, B_);
    softmax_kernel<<<sgrid, 256>>>(interval);

    out_gemm<<<ggrid, 256>>>(E_RV);

    proj_kernel<<<(B_ * L_) / TM, 256>>>(Wo, bo, out);
}

// round 13
// speedup vs baseline: 1.1581x; 1.0058x over previous
#include <cuda_runtime.h>
#include <math.h>

#define B_  2
#define L_  512
#define H_  128
#define NH_ 2
#define DH_ 64
#define RV_ 257   // REL_VOCAB
#define SP  512   // score row pitch
#define RVP 320   // rel-vocab row pitch (5*64)
#define BH_ (B_ * NH_)

// Scratch (allocation-free rule: __device__ globals)
__device__ float g_Q[B_ * L_ * H_];   // pre-scaled by 0.125
__device__ float g_K[B_ * L_ * H_];
__device__ float g_V[B_ * L_ * H_];
__device__ float g_O[B_ * L_ * H_];
__device__ float g_S[BH_ * L_ * SP];    // scores, then softmax weights (in place)
__device__ float g_RS[BH_ * L_ * RVP];  // q . E_RK[r]
__device__ float g_WS[BH_ * L_ * RVP];  // weight histogram over rel vocab

#define TM 8   // rows per GEMM block

// ---------------------------------------------------------------------------
// Kernel 1: fused QKV projections, k-split. grid = (128, 3), 256 threads.
// (unchanged, R12-proven)
// ---------------------------------------------------------------------------
__global__ __launch_bounds__(256) void qkv_kernel(
    const float* __restrict__ query, const float* __restrict__ key,
    const float* __restrict__ value,
    const float* __restrict__ Wq, const float* __restrict__ bq,
    const float* __restrict__ Wk, const float* __restrict__ bk,
    const float* __restrict__ Wv, const float* __restrict__ bv,
    const float* __restrict__ E_PK, const float* __restrict__ E_PV,
    const int* __restrict__ poss)
{
    const int m = blockIdx.y;
    const float *X, *W, *bias, *E;
    float* Y;
    if (m == 0)      { X = query; W = Wq; bias = bq; E = nullptr; Y = g_Q; }
    else if (m == 1) { X = key;   W = Wk; bias = bk; E = E_PK;    Y = g_K; }
    else             { X = value; W = Wv; bias = bv; E = E_PV;    Y = g_V; }

    __shared__ float4 xs[TM][32];
    __shared__ float  part[TM][H_];

    const int r0 = blockIdx.x * TM;
    const int o  = threadIdx.x & 127;
    const int kh = threadIdx.x >> 7;

    ((float4*)xs)[threadIdx.x] =
        ((const float4*)(X + (size_t)r0 * H_))[threadIdx.x];
    __syncthreads();

    float acc[TM];
    #pragma unroll
    for (int rr = 0; rr < TM; rr++) acc[rr] = 0.f;

    const float4* w4p = (const float4*)(W + (size_t)o * H_) + kh * 16;
    #pragma unroll 4
    for (int c = 0; c < 16; c++) {
        float4 w = w4p[c];
        #pragma unroll
        for (int rr = 0; rr < TM; rr++) {
            float4 x = xs[rr][kh * 16 + c];
            acc[rr] = fmaf(w.x, x.x, acc[rr]);
            acc[rr] = fmaf(w.y, x.y, acc[rr]);
            acc[rr] = fmaf(w.z, x.z, acc[rr]);
            acc[rr] = fmaf(w.w, x.w, acc[rr]);
        }
    }

    if (kh == 1) {
        #pragma unroll
        for (int rr = 0; rr < TM; rr++) part[rr][o] = acc[rr];
    }
    __syncthreads();
    if (kh == 0) {
        const float scale = (m == 0) ? 0.125f : 1.0f;
        float bb = bias[o];
        #pragma unroll
        for (int rr = 0; rr < TM; rr++) {
            float v = acc[rr] + part[rr][o] + bb;
            if (E) v += E[(size_t)poss[r0 + rr] * H_ + o];
            Y[(size_t)(r0 + rr) * H_ + o] = v * scale;
        }
    }
}

// ---------------------------------------------------------------------------
// Kernel A: score GEMMs, 32x64 tiles, 128 threads. grid = (16, 13, 4).
//   blockIdx.y < 8 : S tile  (it2, jt) — causal: skip jt > it2/2
//   blockIdx.y >= 8: RS tile (it2, rt=y-8)
// ---------------------------------------------------------------------------
__global__ __launch_bounds__(128) void score_gemm(const float* __restrict__ E_RK)
{
    const int it2 = blockIdx.x;          // 32-row tile index
    const int yy = blockIdx.y;
    const int bh = blockIdx.z;
    const bool smode = (yy < 8);
    const int jt = smode ? yy : (yy - 8);
    if (smode && jt > (it2 >> 1)) return;

    const int b = bh >> 1, h = bh & 1, hd = h * DH_;
    const int i0 = it2 * 32;
    const int j0 = jt * 64;

    __shared__ float As[32 * 68];
    __shared__ float Bs[64 * 68];

    const int tid = threadIdx.x;

    // stage 96 rows x 64 floats: rows 0..31 = A (Q), rows 32..95 = B (K/E_RK)
    #pragma unroll
    for (int p = 0; p < 12; p++) {
        int f = tid + 128 * p;
        int row = f >> 4, c4 = f & 15;
        if (row < 32) {
            *(float4*)(As + row * 68 + 4 * c4) =
                ((const float4*)(g_Q + ((size_t)(b * L_ + i0 + row)) * H_ + hd))[c4];
        } else {
            int r = row - 32;
            float4 vb;
            if (smode) {
                vb = ((const float4*)(g_K + ((size_t)(b * L_ + j0 + r)) * H_ + hd))[c4];
            } else {
                int rr = j0 + r;
                vb = (rr < RV_)
                   ? ((const float4*)(E_RK + (size_t)rr * H_ + hd))[c4]
                   : make_float4(0.f, 0.f, 0.f, 0.f);
            }
            *(float4*)(Bs + r * 68 + 4 * c4) = vb;
        }
    }
    __syncthreads();

    const int tx = tid & 15, ty = tid >> 4;   // ty 0..7
    float acc[4][4];
    #pragma unroll
    for (int ii = 0; ii < 4; ii++)
        #pragma unroll
        for (int jj = 0; jj < 4; jj++) acc[ii][jj] = 0.f;

    #pragma unroll 4
    for (int kc = 0; kc < 16; kc++) {
        float4 a[4], bb[4];
        #pragma unroll
        for (int u = 0; u < 4; u++) {
            a[u]  = *(const float4*)(As + (4 * ty + u) * 68 + 4 * kc);
            bb[u] = *(const float4*)(Bs + (4 * tx + u) * 68 + 4 * kc);
        }
        #pragma unroll
        for (int ii = 0; ii < 4; ii++)
            #pragma unroll
            for (int jj = 0; jj < 4; jj++) {
                acc[ii][jj] = fmaf(a[ii].x, bb[jj].x, acc[ii][jj]);
                acc[ii][jj] = fmaf(a[ii].y, bb[jj].y, acc[ii][jj]);
                acc[ii][jj] = fmaf(a[ii].z, bb[jj].z, acc[ii][jj]);
                acc[ii][jj] = fmaf(a[ii].w, bb[jj].w, acc[ii][jj]);
            }
    }

    #pragma unroll
    for (int ii = 0; ii < 4; ii++) {
        int gi = i0 + 4 * ty + ii;
        float4 v = make_float4(acc[ii][0], acc[ii][1], acc[ii][2], acc[ii][3]);
        if (smode)
            *(float4*)(g_S + ((size_t)bh * L_ + gi) * SP + j0 + 4 * tx) = v;
        else
            *(float4*)(g_RS + ((size_t)bh * L_ + gi) * RVP + j0 + 4 * tx) = v;
    }
}

// ---------------------------------------------------------------------------
// Kernel B: softmax, warp-per-row. grid = (64, NH, B), 256 threads = 8 rows.
// (unchanged, R12-proven)
// ---------------------------------------------------------------------------
__global__ __launch_bounds__(256) void softmax_kernel(const int* __restrict__ interval)
{
    const int tile = (L_ / 8 - 1) - (int)blockIdx.x;
    const int h = blockIdx.y;
    const int b = blockIdx.z;
    const int bh = b * NH_ + h;
    const int warp = threadIdx.x >> 5;
    const int lane = threadIdx.x & 31;

    const int i = tile * 8 + warp;
    const int n = i + 1;
    const int jpad = ((i >> 6) + 1) * 64;

    __shared__ float ws[8][RVP];

    for (int r = lane; r < RVP; r += 32) ws[warp][r] = 0.f;

    {
        float* orow = g_O + ((size_t)(b * L_ + i)) * H_ + h * DH_;
        orow[lane] = 0.f;
        orow[lane + 32] = 0.f;
    }

    const int*   iv    = interval + ((size_t)(b * L_ + i)) * L_;
    const float* RSrow = g_RS + ((size_t)bh * L_ + i) * RVP;
    float*       Srow  = g_S + ((size_t)bh * L_ + i) * SP;

    float sreg[16];
    int   ireg[16];

    float m = -INFINITY;
    #pragma unroll
    for (int t = 0; t < 16; t++) {
        int j = lane + 32 * t;
        if (j < n) {
            int idx = iv[j];
            ireg[t] = idx;
            float s = Srow[j] + RSrow[idx];
            sreg[t] = s;
            m = fmaxf(m, s);
        }
    }
    #pragma unroll
    for (int off = 16; off > 0; off >>= 1)
        m = fmaxf(m, __shfl_xor_sync(0xffffffffu, m, off));

    float sum = 0.f;
    #pragma unroll
    for (int t = 0; t < 16; t++) {
        int j = lane + 32 * t;
        if (j < n) {
            float e = __expf(sreg[t] - m);
            sreg[t] = e;
            sum += e;
        }
    }
    #pragma unroll
    for (int off = 16; off > 0; off >>= 1)
        sum += __shfl_xor_sync(0xffffffffu, sum, off);
    float inv = 1.f / sum;

    #pragma unroll
    for (int t = 0; t < 16; t++) {
        int j = lane + 32 * t;
        if (j < n) {
            float w = sreg[t] * inv;
            Srow[j] = w;
            atomicAdd(&ws[warp][ireg[t]], w);
        }
    }
    for (int j = n + lane; j < jpad; j += 32) Srow[j] = 0.f;

    __syncwarp();

    float* WSrow = g_WS + ((size_t)bh * L_ + i) * RVP;
    for (int r = lane; r < RVP; r += 32) WSrow[r] = ws[warp][r];
}

// ---------------------------------------------------------------------------
// Kernel C: output GEMMs, 32x64 tiles, 128 threads, atomic split-k.
// grid = (16, 13, 4).
// ---------------------------------------------------------------------------
__global__ __launch_bounds__(128) void out_gemm(const float* __restrict__ E_RV)
{
    const int it2 = blockIdx.x;
    const int yy = blockIdx.y;
    const int bh = blockIdx.z;
    const bool smode = (yy < 8);
    const int jt = smode ? yy : (yy - 8);
    if (smode && jt > (it2 >> 1)) return;

    const int b = bh >> 1, h = bh & 1, hd = h * DH_;
    const int i0 = it2 * 32;
    const int k0 = jt * 64;

    __shared__ float Ws[32 * 68];   // weights: [i][k]
    __shared__ float Vs[64 * 68];   // values:  [k][d]

    const int tid = threadIdx.x;

    #pragma unroll
    for (int p = 0; p < 12; p++) {
        int f = tid + 128 * p;
        int row = f >> 4, c4 = f & 15;
        if (row < 32) {
            float4 vw;
            if (smode)
                vw = *(const float4*)(g_S + ((size_t)bh * L_ + i0 + row) * SP + k0 + 4 * c4);
            else
                vw = *(const float4*)(g_WS + ((size_t)bh * L_ + i0 + row) * RVP + k0 + 4 * c4);
            *(float4*)(Ws + row * 68 + 4 * c4) = vw;
        } else {
            int r = row - 32;
            float4 vv;
            if (smode) {
                vv = ((const float4*)(g_V + ((size_t)(b * L_ + k0 + r)) * H_ + hd))[c4];
            } else {
                int rr = k0 + r;
                vv = (rr < RV_)
                   ? ((const float4*)(E_RV + (size_t)rr * H_ + hd))[c4]
                   : make_float4(0.f, 0.f, 0.f, 0.f);
            }
            *(float4*)(Vs + r * 68 + 4 * c4) = vv;
        }
    }
    __syncthreads();

    const int tx = tid & 15, ty = tid >> 4;   // ty 0..7
    float acc[4][4];
    #pragma unroll
    for (int ii = 0; ii < 4; ii++)
        #pragma unroll
        for (int jj = 0; jj < 4; jj++) acc[ii][jj] = 0.f;

    #pragma unroll 8
    for (int k = 0; k < 64; k++) {
        float4 bv = *(const float4*)(Vs + k * 68 + 4 * tx);
        float a0 = Ws[(4 * ty + 0) * 68 + k];
        float a1 = Ws[(4 * ty + 1) * 68 + k];
        float a2 = Ws[(4 * ty + 2) * 68 + k];
        float a3 = Ws[(4 * ty + 3) * 68 + k];
        acc[0][0] = fmaf(a0, bv.x, acc[0][0]); acc[0][1] = fmaf(a0, bv.y, acc[0][1]);
        acc[0][2] = fmaf(a0, bv.z, acc[0][2]); acc[0][3] = fmaf(a0, bv.w, acc[0][3]);
        acc[1][0] = fmaf(a1, bv.x, acc[1][0]); acc[1][1] = fmaf(a1, bv.y, acc[1][1]);
        acc[1][2] = fmaf(a1, bv.z, acc[1][2]); acc[1][3] = fmaf(a1, bv.w, acc[1][3]);
        acc[2][0] = fmaf(a2, bv.x, acc[2][0]); acc[2][1] = fmaf(a2, bv.y, acc[2][1]);
        acc[2][2] = fmaf(a2, bv.z, acc[2][2]); acc[2][3] = fmaf(a2, bv.w, acc[2][3]);
        acc[3][0] = fmaf(a3, bv.x, acc[3][0]); acc[3][1] = fmaf(a3, bv.y, acc[3][1]);
        acc[3][2] = fmaf(a3, bv.z, acc[3][2]); acc[3][3] = fmaf(a3, bv.w, acc[3][3]);
    }

    #pragma unroll
    for (int ii = 0; ii < 4; ii++) {
        float* orow = g_O + ((size_t)(b * L_ + i0 + 4 * ty + ii)) * H_ + hd + 4 * tx;
        #pragma unroll
        for (int jj = 0; jj < 4; jj++)
            atomicAdd(orow + jj, acc[ii][jj]);
    }
}

// ---------------------------------------------------------------------------
// Kernel 3: output projection, k-split. grid = 128, 256 threads.
// (unchanged, R12-proven)
// ---------------------------------------------------------------------------
__global__ __launch_bounds__(256) void proj_kernel(
    const float* __restrict__ Wo, const float* __restrict__ bo,
    float* __restrict__ out)
{
    __shared__ float4 xs[TM][32];
    __shared__ float  part[TM][H_];

    const int r0 = blockIdx.x * TM;
    const int o  = threadIdx.x & 127;
    const int kh = threadIdx.x >> 7;

    ((float4*)xs)[threadIdx.x] =
        ((const float4*)(g_O + (size_t)r0 * H_))[threadIdx.x];
    __syncthreads();

    float acc[TM];
    #pragma unroll
    for (int rr = 0; rr < TM; rr++) acc[rr] = 0.f;

    const float4* w4p = (const float4*)(Wo + (size_t)o * H_) + kh * 16;
    #pragma unroll 4
    for (int c = 0; c < 16; c++) {
        float4 w = w4p[c];
        #pragma unroll
        for (int rr = 0; rr < TM; rr++) {
            float4 x = xs[rr][kh * 16 + c];
            acc[rr] = fmaf(w.x, x.x, acc[rr]);
            acc[rr] = fmaf(w.y, x.y, acc[rr]);
            acc[rr] = fmaf(w.z, x.z, acc[rr]);
            acc[rr] = fmaf(w.w, x.w, acc[rr]);
        }
    }

    if (kh == 1) {
        #pragma unroll
        for (int rr = 0; rr < TM; rr++) part[rr][o] = acc[rr];
    }
    __syncthreads();
    if (kh == 0) {
        float bb = bo[o];
        #pragma unroll
        for (int rr = 0; rr < TM; rr++) {
            float v = acc[rr] + part[rr][o] + bb;
            if (isnan(v)) v = 0.f;
            out[(size_t)(r0 + rr) * H_ + o] = v;
        }
    }
}

// ---------------------------------------------------------------------------
extern "C" void kernel_launch(void* const* d_in, const int* in_sizes, int n_in,
                              void* d_out, int out_size)
{
    const float* query    = (const float*)d_in[0];
    const float* key      = (const float*)d_in[1];
    const float* value    = (const float*)d_in[2];
    const float* Wq       = (const float*)d_in[3];
    const float* bq       = (const float*)d_in[4];
    const float* Wk       = (const float*)d_in[5];
    const float* bk       = (const float*)d_in[6];
    const float* Wv       = (const float*)d_in[7];
    const float* bv       = (const float*)d_in[8];
    const float* Wo       = (const float*)d_in[9];
    const float* bo       = (const float*)d_in[10];
    const float* E_PK     = (const float*)d_in[11];
    const float* E_PV     = (const float*)d_in[12];
    const float* E_RK     = (const float*)d_in[13];
    const float* E_RV     = (const float*)d_in[14];
    const int*   poss     = (const int*)d_in[15];
    const int*   interval = (const int*)d_in[16];
    // d_in[17] = attn_mask (exactly tril; causal is hardcoded)

    float* out = (float*)d_out;

    dim3 qgrid((B_ * L_) / TM, 3);
    qkv_kernel<<<qgrid, 256>>>(
        query, key, value, Wq, bq, Wk, bk, Wv, bv, E_PK, E_PV, poss);

    dim3 ggrid(16, 13, BH_);
    score_gemm<<<ggrid, 128>>>(E_RK);

    dim3 sgrid(L_ / 8, NH_, B_);
    softmax_kernel<<<sgrid, 256>>>(interval);

    out_gemm<<<ggrid, 128>>>(E_RV);

    proj_kernel<<<(B_ * L_) / TM, 256>>>(Wo, bo, out);
}